// round 1
// baseline (speedup 1.0000x reference)
#include <cuda_runtime.h>

#define MAXN 512

// Scratch (allocation-free rule: device globals)
__device__ float g_D[MAXN * MAXN];   // pairwise distances, diag = 1e6
__device__ float g_sq[MAXN];         // squared row norms
__device__ float g_prec[MAXN];       // per-query soft precision

__device__ __forceinline__ float sigmoidf_(float x) {
    // numerically stable: only exp of non-positive arguments
    if (x >= 0.f) {
        float e = __expf(-x);
        return 1.f / (1.f + e);
    } else {
        float e = __expf(x);
        return e / (1.f + e);
    }
}

// --- Kernel 0: squared norms per row ---
__global__ void k_rowsq(const float* __restrict__ emb, int n, int dim) {
    int i = blockIdx.x * blockDim.x + threadIdx.x;
    if (i >= n) return;
    const float* r = emb + (size_t)i * dim;
    float acc = 0.f;
    for (int k = 0; k < dim; k += 4) {
        float4 v = *reinterpret_cast<const float4*>(r + k);
        acc = fmaf(v.x, v.x, acc);
        acc = fmaf(v.y, v.y, acc);
        acc = fmaf(v.z, v.z, acc);
        acc = fmaf(v.w, v.w, acc);
    }
    g_sq[i] = acc;
}

// --- Kernel 1: D[q][j] = sqrt(max(sq[q]+sq[j]-2*dot, 1e-12)), diag = 1e6 ---
// classic 32x32 shared-memory tiled Gram matrix
__global__ void k_dist(const float* __restrict__ emb, int n, int dim) {
    __shared__ float As[32][33];
    __shared__ float Bs[32][33];
    int tx = threadIdx.x, ty = threadIdx.y;
    int q = blockIdx.y * 32 + ty;
    int j = blockIdx.x * 32 + tx;
    float acc = 0.f;
    for (int kc = 0; kc < dim; kc += 32) {
        int ra = blockIdx.y * 32 + ty;
        int rb = blockIdx.x * 32 + ty;
        int kk = kc + tx;
        As[ty][tx] = (ra < n && kk < dim) ? emb[(size_t)ra * dim + kk] : 0.f;
        Bs[ty][tx] = (rb < n && kk < dim) ? emb[(size_t)rb * dim + kk] : 0.f;
        __syncthreads();
#pragma unroll
        for (int k = 0; k < 32; k++)
            acc = fmaf(As[ty][k], Bs[tx][k], acc);
        __syncthreads();
    }
    if (q < n && j < n) {
        float d2 = g_sq[q] + g_sq[j] - 2.f * acc;
        float d = sqrtf(fmaxf(d2, 1e-12f));
        g_D[q * n + j] = (q == j) ? 1e6f : d;
    }
}

// --- Kernel 2: per-query soft precision. One block per query. ---
// Only computes rank[q,j] for j in the ground-truth set of q (same label, j!=q):
// ~7 per query instead of 512 -> ~70x less sigmoid work than the naive form.
__global__ void k_prec(const int* __restrict__ labels, int n, float Kf) {
    extern __shared__ char smem_raw[];
    float* sd = (float*)smem_raw;                     // D row of q (n floats)
    int* slab = (int*)(smem_raw + n * sizeof(float)); // labels (n ints)

    const int q = blockIdx.x;
    const int tid = threadIdx.x;
    const int NT = blockDim.x;

    for (int m = tid; m < n; m += NT) {
        sd[m] = g_D[q * n + m];
        slab[m] = labels[m];
    }
    __syncthreads();

    __shared__ float wsum[32];
    __shared__ float s_num;
    if (tid == 0) s_num = 0.f;

    const int lq = slab[q];
    const int lane = tid & 31;
    const int wid = tid >> 5;
    const int nw = NT >> 5;
    int gtc = 0;

    const float invT2 = 100.0f;  // 1/T2

    for (int j = 0; j < n; j++) {
        // uniform across block: no divergence
        if (j == q || slab[j] != lq) continue;
        gtc++;
        float dj = sd[j];
        float part = 0.f;
        for (int m = tid; m < n; m += NT)
            part += sigmoidf_((dj - sd[m]) * invT2);
#pragma unroll
        for (int o = 16; o; o >>= 1)
            part += __shfl_xor_sync(0xffffffffu, part, o);
        if (lane == 0) wsum[wid] = part;
        __syncthreads();
        if (tid == 0) {
            float rank = 0.f;
            for (int w = 0; w < nw; w++) rank += wsum[w];
            s_num += sigmoidf_(Kf - rank);  // T1 = 1
        }
        __syncthreads();
    }

    if (tid == 0) {
        float den = fminf((float)gtc, Kf);
        g_prec[q] = s_num / den;  // 0/0 -> NaN matches reference semantics
    }
}

// --- Kernel 3: loss = 1 - mean(prec) ---
__global__ void k_final(float* __restrict__ out, int n) {
    __shared__ float s[512];
    int t = threadIdx.x;
    float v = 0.f;
    for (int i = t; i < n; i += 512) v += g_prec[i];
    s[t] = v;
    __syncthreads();
    for (int st = 256; st; st >>= 1) {
        if (t < st) s[t] += s[t + st];
        __syncthreads();
    }
    if (t == 0) out[0] = 1.0f - s[0] / (float)n;
}

extern "C" void kernel_launch(void* const* d_in, const int* in_sizes, int n_in,
                              void* d_out, int out_size) {
    const float* emb = (const float*)d_in[0];
    const int* labels = (const int*)d_in[1];
    const int n = in_sizes[1];            // 512
    const int dim = in_sizes[0] / n;      // 384

    k_rowsq<<<(n + 255) / 256, 256>>>(emb, n, dim);

    dim3 bt(32, 32);
    dim3 gd((n + 31) / 32, (n + 31) / 32);
    k_dist<<<gd, bt>>>(emb, n, dim);

    size_t smem = (size_t)n * (sizeof(float) + sizeof(int));
    k_prec<<<n, 256, smem>>>(labels, n, 5.0f);

    k_final<<<1, 512>>>((float*)d_out, n);
}

// round 2
// speedup vs baseline: 1.3393x; 1.3393x over previous
#include <cuda_runtime.h>

#define NMAX 512

// Scratch (device globals per allocation-free rule)
__device__ float g_G[NMAX * NMAX];  // raw Gram matrix (dot products)
__device__ float g_sq[NMAX];        // diagonal = squared norms
__device__ float g_prec[NMAX];      // per-query soft precision
__device__ int   g_ctr;             // arrival counter (zero-initialized; reset each replay)

__device__ __forceinline__ float sigmoidf_(float x) {
    if (x >= 0.f) { float e = __expf(-x); return 1.f / (1.f + e); }
    else          { float e = __expf(x);  return e / (1.f + e); }
}

// ---------------- Kernel 1: Gram matrix (register-tiled) ----------------
// BM=32 (q) x BN=64 (m) tiles, 256 threads, each thread computes 2x4.
// 128 blocks: one wave on the chip. Also extracts the diagonal into g_sq.
#define BM 32
#define BN 64
#define BK 32

__global__ void __launch_bounds__(256, 1) k_gram(const float* __restrict__ emb, int n, int dim) {
    __shared__ float sa[BK][BM + 2];  // k-major; +2 keeps LDS.64 reads aligned, 2-way store conflicts only
    __shared__ float sb[BK][BN];      // k-major; LDS.128 reads conflict-free

    const int t  = threadIdx.x;
    const int tx = t & 15;   // m micro-col (4 outputs)
    const int ty = t >> 4;   // q micro-row (2 outputs)
    const int q0 = blockIdx.y * BM;
    const int m0 = blockIdx.x * BN;

    float acc[2][4] = {{0.f,0.f,0.f,0.f},{0.f,0.f,0.f,0.f}};

    for (int kt = 0; kt < dim; kt += BK) {
        // Load A tile: 32 rows x 32 k (1024 elems, 1 float4/thread), transpose to k-major
        {
            int r = t >> 3;            // 0..31
            int c = (t & 7) * 4;       // 0..28
            float4 v = *reinterpret_cast<const float4*>(&emb[(size_t)(q0 + r) * dim + kt + c]);
            sa[c + 0][r] = v.x; sa[c + 1][r] = v.y; sa[c + 2][r] = v.z; sa[c + 3][r] = v.w;
        }
        // Load B tile: 64 rows x 32 k (2048 elems, 2 float4/thread), transpose to k-major
        {
            int r = t >> 2;            // 0..63
            int c = (t & 3) * 8;       // 0,8,16,24
            const float* p = &emb[(size_t)(m0 + r) * dim + kt + c];
            float4 v0 = *reinterpret_cast<const float4*>(p);
            float4 v1 = *reinterpret_cast<const float4*>(p + 4);
            sb[c + 0][r] = v0.x; sb[c + 1][r] = v0.y; sb[c + 2][r] = v0.z; sb[c + 3][r] = v0.w;
            sb[c + 4][r] = v1.x; sb[c + 5][r] = v1.y; sb[c + 6][r] = v1.z; sb[c + 7][r] = v1.w;
        }
        __syncthreads();
#pragma unroll
        for (int k = 0; k < BK; k++) {
            float a0 = sa[k][ty * 2 + 0];
            float a1 = sa[k][ty * 2 + 1];
            float4 bv = *reinterpret_cast<const float4*>(&sb[k][tx * 4]);
            acc[0][0] = fmaf(a0, bv.x, acc[0][0]);
            acc[0][1] = fmaf(a0, bv.y, acc[0][1]);
            acc[0][2] = fmaf(a0, bv.z, acc[0][2]);
            acc[0][3] = fmaf(a0, bv.w, acc[0][3]);
            acc[1][0] = fmaf(a1, bv.x, acc[1][0]);
            acc[1][1] = fmaf(a1, bv.y, acc[1][1]);
            acc[1][2] = fmaf(a1, bv.z, acc[1][2]);
            acc[1][3] = fmaf(a1, bv.w, acc[1][3]);
        }
        __syncthreads();
    }

#pragma unroll
    for (int i = 0; i < 2; i++) {
        int q = q0 + ty * 2 + i;
        int m = m0 + tx * 4;
        float4 v = make_float4(acc[i][0], acc[i][1], acc[i][2], acc[i][3]);
        *reinterpret_cast<float4*>(&g_G[(size_t)q * n + m]) = v;
        if (q >= m && q < m + 4) g_sq[q] = acc[i][q - m];  // diagonal = squared norm
    }
}

// ---------------- Kernel 2: per-query soft precision + final reduce ----------------
// One block per query. Rebuilds dist row from Gram + diag, does the gt-only
// soft-rank loop (only ~|class| columns, not all 512). Last block finishes.
__global__ void __launch_bounds__(256) k_prec(const int* __restrict__ labels,
                                              float* __restrict__ out,
                                              int n, float Kf) {
    __shared__ float sd[NMAX];
    __shared__ int   slab[NMAX];
    __shared__ float wsum[8];
    __shared__ float s_num;
    __shared__ int   s_last;

    const int q   = blockIdx.x;
    const int tid = threadIdx.x;
    const int NT  = blockDim.x;

    const float sqq = g_sq[q];
    for (int m = tid; m < n; m += NT) {
        float g  = g_G[(size_t)q * n + m];
        float d2 = sqq + g_sq[m] - 2.f * g;
        sd[m]    = (m == q) ? 1e6f : sqrtf(fmaxf(d2, 1e-12f));
        slab[m]  = labels[m];
    }
    if (tid == 0) { s_num = 0.f; s_last = 0; }
    __syncthreads();

    const int   lq    = slab[q];
    const int   lane  = tid & 31;
    const int   wid   = tid >> 5;
    const int   nw    = NT >> 5;
    const float invT2 = 100.0f;
    int gtc = 0;

    for (int j = 0; j < n; j++) {
        if (j == q || slab[j] != lq) continue;   // uniform across block
        gtc++;
        float dj = sd[j];
        float part = 0.f;
        for (int m = tid; m < n; m += NT)
            part += sigmoidf_((dj - sd[m]) * invT2);
#pragma unroll
        for (int o = 16; o; o >>= 1)
            part += __shfl_xor_sync(0xffffffffu, part, o);
        if (lane == 0) wsum[wid] = part;
        __syncthreads();
        if (tid == 0) {
            float rank = 0.f;
            for (int w = 0; w < nw; w++) rank += wsum[w];
            s_num += sigmoidf_(Kf - rank);       // T1 = 1
        }
        __syncthreads();
    }

    if (tid == 0) {
        float den = fminf((float)gtc, Kf);
        g_prec[q] = s_num / den;                 // 0/0 -> NaN matches reference
        __threadfence();
        int old = atomicAdd(&g_ctr, 1);
        if (old == gridDim.x - 1) s_last = 1;
    }
    __syncthreads();

    if (s_last) {
        // deterministic fixed-order final reduce by the last block
        __threadfence();
        float v = 0.f;
        for (int i = tid; i < n; i += NT) v += g_prec[i];
#pragma unroll
        for (int o = 16; o; o >>= 1)
            v += __shfl_xor_sync(0xffffffffu, v, o);
        if (lane == 0) wsum[wid] = v;
        __syncthreads();
        if (tid == 0) {
            float s = 0.f;
            for (int w = 0; w < nw; w++) s += wsum[w];
            out[0] = 1.0f - s / (float)n;
            g_ctr = 0;                            // reset for next graph replay
        }
    }
}

extern "C" void kernel_launch(void* const* d_in, const int* in_sizes, int n_in,
                              void* d_out, int out_size) {
    const float* emb    = (const float*)d_in[0];
    const int*   labels = (const int*)d_in[1];
    const int n   = in_sizes[1];        // 512
    const int dim = in_sizes[0] / n;    // 384

    dim3 gd(n / BN, n / BM);            // 8 x 16 = 128 blocks
    k_gram<<<gd, 256>>>(emb, n, dim);
    k_prec<<<n, 256>>>(labels, (float*)d_out, n, 5.0f);
}

// round 3
// speedup vs baseline: 3.2047x; 2.3928x over previous
#include <cuda_runtime.h>

#define NMAX 512

// Scratch (device globals per allocation-free rule)
__device__ float g_G[NMAX * NMAX];  // raw Gram matrix (dot products)
__device__ float g_sq[NMAX];        // diagonal = squared norms
__device__ float g_prec[NMAX];      // per-query soft precision
__device__ int   g_ctr;             // arrival counter (zero-init; reset each replay)

__device__ __forceinline__ float sigmoidf_(float x) {
    // numerically stable full-range sigmoid (used ~7x per query only)
    if (x >= 0.f) { float e = __expf(-x); return 1.f / (1.f + e); }
    else          { float e = __expf(x);  return e / (1.f + e); }
}

__device__ __forceinline__ float sig_sat(float x) {
    // saturating sigmoid: |x|>18 -> 0/1 (err < 1.6e-8), else exact.
    // Most arguments here are +-100s, so MUFU work is rare.
    if (x > 18.f)  return 1.f;
    if (x < -18.f) return 0.f;
    float e = __expf(-x);
    return 1.f / (1.f + e);
}

// ---------------- Kernel 1: Gram matrix (register-tiled) ----------------
#define BM 32
#define BN 64
#define BK 32

__global__ void __launch_bounds__(256, 1) k_gram(const float* __restrict__ emb, int n, int dim) {
    __shared__ float sa[BK][BM + 2];
    __shared__ float sb[BK][BN];

    const int t  = threadIdx.x;
    const int tx = t & 15;
    const int ty = t >> 4;
    const int q0 = blockIdx.y * BM;
    const int m0 = blockIdx.x * BN;

    float acc[2][4] = {{0.f,0.f,0.f,0.f},{0.f,0.f,0.f,0.f}};

    for (int kt = 0; kt < dim; kt += BK) {
        {
            int r = t >> 3;
            int c = (t & 7) * 4;
            float4 v = *reinterpret_cast<const float4*>(&emb[(size_t)(q0 + r) * dim + kt + c]);
            sa[c + 0][r] = v.x; sa[c + 1][r] = v.y; sa[c + 2][r] = v.z; sa[c + 3][r] = v.w;
        }
        {
            int r = t >> 2;
            int c = (t & 3) * 8;
            const float* p = &emb[(size_t)(m0 + r) * dim + kt + c];
            float4 v0 = *reinterpret_cast<const float4*>(p);
            float4 v1 = *reinterpret_cast<const float4*>(p + 4);
            sb[c + 0][r] = v0.x; sb[c + 1][r] = v0.y; sb[c + 2][r] = v0.z; sb[c + 3][r] = v0.w;
            sb[c + 4][r] = v1.x; sb[c + 5][r] = v1.y; sb[c + 6][r] = v1.z; sb[c + 7][r] = v1.w;
        }
        __syncthreads();
#pragma unroll
        for (int k = 0; k < BK; k++) {
            float a0 = sa[k][ty * 2 + 0];
            float a1 = sa[k][ty * 2 + 1];
            float4 bv = *reinterpret_cast<const float4*>(&sb[k][tx * 4]);
            acc[0][0] = fmaf(a0, bv.x, acc[0][0]);
            acc[0][1] = fmaf(a0, bv.y, acc[0][1]);
            acc[0][2] = fmaf(a0, bv.z, acc[0][2]);
            acc[0][3] = fmaf(a0, bv.w, acc[0][3]);
            acc[1][0] = fmaf(a1, bv.x, acc[1][0]);
            acc[1][1] = fmaf(a1, bv.y, acc[1][1]);
            acc[1][2] = fmaf(a1, bv.z, acc[1][2]);
            acc[1][3] = fmaf(a1, bv.w, acc[1][3]);
        }
        __syncthreads();
    }

#pragma unroll
    for (int i = 0; i < 2; i++) {
        int q = q0 + ty * 2 + i;
        int m = m0 + tx * 4;
        float4 v = make_float4(acc[i][0], acc[i][1], acc[i][2], acc[i][3]);
        *reinterpret_cast<float4*>(&g_G[(size_t)q * n + m]) = v;
        if (q >= m && q < m + 4) g_sq[q] = acc[i][q - m];
    }
}

// ---------------- Kernel 2: per-query soft precision (warp-per-gt) ----------------
__global__ void __launch_bounds__(256) k_prec(const int* __restrict__ labels,
                                              float* __restrict__ out,
                                              int n, float Kf) {
    __shared__ float sd[NMAX];     // distance row of query q
    __shared__ int   sgt[64];      // compacted gt indices (ascending)
    __shared__ float srank[64];    // per-gt soft rank
    __shared__ int   s_gtc;
    __shared__ float wsum[8];
    __shared__ int   s_last;

    const int q    = blockIdx.x;
    const int tid  = threadIdx.x;
    const int NT   = blockDim.x;
    const int lane = tid & 31;
    const int wid  = tid >> 5;

    // Build distance row from Gram + diag; load labels into registers en route
    const float sqq = g_sq[q];
    const int lq = labels[q];
    for (int m = tid; m < n; m += NT) {
        float g  = g_G[(size_t)q * n + m];
        float d2 = sqq + g_sq[m] - 2.f * g;
        sd[m]    = (m == q) ? 1e6f : sqrtf(fmaxf(d2, 1e-12f));
    }
    if (tid == 0) s_last = 0;

    // Warp 0: deterministic (ascending-j) gt compaction
    if (wid == 0) {
        int cnt = 0;
        for (int base = 0; base < n; base += 32) {
            int j = base + lane;
            bool f = (j != q) && (labels[j] == lq);
            unsigned b = __ballot_sync(0xffffffffu, f);
            int pos = cnt + __popc(b & ((1u << lane) - 1u));
            if (f && pos < 64) sgt[pos] = j;
            cnt += __popc(b);
        }
        if (lane == 0) s_gtc = (cnt < 64) ? cnt : 64;
    }
    __syncthreads();

    const int gtc = s_gtc;
    const float invT2 = 100.0f;

    // Each warp owns one gt entry: full 512-term soft rank, no block barriers
    for (int g = wid; g < gtc; g += (NT >> 5)) {
        float dj = sd[sgt[g]];
        float part = 0.f;
        for (int m = lane; m < n; m += 32)
            part += sig_sat((dj - sd[m]) * invT2);
#pragma unroll
        for (int o = 16; o; o >>= 1)
            part += __shfl_xor_sync(0xffffffffu, part, o);
        if (lane == 0) srank[g] = part;
    }
    __syncthreads();

    if (tid == 0) {
        float num = 0.f;
        for (int g = 0; g < gtc; g++)           // fixed order: deterministic
            num += sigmoidf_(Kf - srank[g]);    // T1 = 1
        float den = fminf((float)gtc, Kf);
        g_prec[q] = num / den;                  // 0/0 -> NaN matches reference
        __threadfence();
        int old = atomicAdd(&g_ctr, 1);
        if (old == gridDim.x - 1) s_last = 1;
    }
    __syncthreads();

    if (s_last) {
        __threadfence();
        float v = 0.f;
        for (int i = tid; i < n; i += NT) v += g_prec[i];
#pragma unroll
        for (int o = 16; o; o >>= 1)
            v += __shfl_xor_sync(0xffffffffu, v, o);
        if (lane == 0) wsum[wid] = v;
        __syncthreads();
        if (tid == 0) {
            float s = 0.f;
            for (int w = 0; w < (NT >> 5); w++) s += wsum[w];
            out[0] = 1.0f - s / (float)n;
            g_ctr = 0;                          // reset for next graph replay
        }
    }
}

extern "C" void kernel_launch(void* const* d_in, const int* in_sizes, int n_in,
                              void* d_out, int out_size) {
    const float* emb    = (const float*)d_in[0];
    const int*   labels = (const int*)d_in[1];
    const int n   = in_sizes[1];        // 512
    const int dim = in_sizes[0] / n;    // 384

    dim3 gd(n / BN, n / BM);            // 128 blocks
    k_gram<<<gd, 256>>>(emb, n, dim);
    k_prec<<<n, 256>>>(labels, (float*)d_out, n, 5.0f);
}